// round 10
// baseline (speedup 1.0000x reference)
#include <cuda_runtime.h>
#include <cuda_fp16.h>
#include <math.h>
#include <cstdint>

// ---------------- problem constants ----------------
#define NB     4
#define L_SP   5440
#define N_VT   8
#define LQ     (L_SP + N_VT)      // 5448
#define DM     256
#define DF     1024
#define NH     8
#define DH     32
#define NLEV   4
#define NPTS   4
#define ROWS   (NB * LQ)          // 21792
#define EPSLN  1e-5f

__device__ __constant__ int c_H[NLEV]     = {64, 32, 16, 8};
__device__ __constant__ int c_W[NLEV]     = {64, 32, 16, 8};
__device__ __constant__ int c_start[NLEV] = {0, 4096, 5120, 5376};

// ---------------- scratch (device globals; no allocs) ----------------
static __device__ float g_v   [ (size_t)ROWS * DM ];   // v_in fp32 (residual 1)
static __device__ float g_off [ (size_t)ROWS * DM ];
static __device__ float g_attn[ (size_t)ROWS * 128 ];  // raw logits (softmax fused in sample)
static __device__ float g_tmp [ (size_t)ROWS * DM ];
static __device__ float g_x   [ (size_t)ROWS * DM ];

static __device__ __half g_valh[ (size_t)ROWS * DM ];  // value projection (sampling source)
static __device__ __half g_qh [ (size_t)ROWS * DM ];
static __device__ __half g_vh [ (size_t)ROWS * DM ];
static __device__ __half g_sh [ (size_t)ROWS * DM ];
static __device__ __half g_xh [ (size_t)ROWS * DM ];
static __device__ __half g_h1h[ (size_t)ROWS * DF ];

// weights (concatenated fp16): Wv | Wo | Wa | Wout | W1 | W2
#define WOFF_V    0
#define WOFF_O    65536
#define WOFF_A    131072
#define WOFF_OUT  163840
#define WOFF_1    229376
#define WOFF_2    491520
#define WTOT      753664
static __device__ __half g_wh[WTOT];

// ---------------- helpers ----------------
__device__ __forceinline__ uint32_t smem_to_u32(const void* p) {
    uint32_t a;
    asm("{ .reg .u64 t; cvta.to.shared.u64 t, %1; cvt.u32.u64 %0, t; }" : "=r"(a) : "l"(p));
    return a;
}

#define LDSM_X4(r, addr) \
    asm volatile("ldmatrix.sync.aligned.m8n8.x4.shared.b16 {%0,%1,%2,%3}, [%4];" \
        : "=r"((r)[0]), "=r"((r)[1]), "=r"((r)[2]), "=r"((r)[3]) : "r"(addr))

#define MMA_F16(d, a, b) \
    asm volatile("mma.sync.aligned.m16n8k16.row.col.f32.f16.f16.f32 " \
        "{%0,%1,%2,%3}, {%4,%5,%6,%7}, {%8,%9}, {%0,%1,%2,%3};" \
        : "+f"((d)[0]), "+f"((d)[1]), "+f"((d)[2]), "+f"((d)[3]) \
        : "r"((a)[0]), "r"((a)[1]), "r"((a)[2]), "r"((a)[3]), \
          "r"((b)[0]), "r"((b)[1]))

__device__ __forceinline__ void cp_async16(uint32_t dst, const void* src, bool pred) {
    int sz = pred ? 16 : 0;
    asm volatile("cp.async.cg.shared.global [%0], [%1], 16, %2;"
        :: "r"(dst), "l"(src), "r"(sz) : "memory");
}
#define CP_COMMIT() asm volatile("cp.async.commit_group;" ::: "memory")
#define CP_WAIT2()  asm volatile("cp.async.wait_group 2;" ::: "memory")

// swizzled byte offset within rows of 128 bytes
__device__ __forceinline__ uint32_t swz(uint32_t row, uint32_t kb) {
    return row * 128u + (kb ^ ((row & 7u) << 4));
}

// ---------------- pipelined warp-MMA 1-term fp16 GEMM ----------------
// C = Ah @ Bh^T + bias. CTA tile 128x64, BK=64, 256 threads (8 warps, 4m x 2n),
// warp tile 32x32. 3-stage cp.async; stage = 24KB (AH 16K, BH 8K). 3 CTAs/SM (72KB each).
#define STG_BYTES 24576
#define SB_AH 0
#define SB_BH 16384
#define GSM_TOTAL (3 * STG_BYTES)   // 73728

extern __shared__ char dyn_smem[];

__device__ __forceinline__ void gemm_issue_stage(
    uint32_t sb, const __half* Ah, const __half* Bh,
    int bm, int bn, int k0, int M, int K, int tid, bool active)
{
#pragma unroll
    for (int t = 0; t < 4; t++) {
        int idx = t * 256 + tid;
        int row = idx >> 3, seg = idx & 7;
        uint32_t so = swz((uint32_t)row, (uint32_t)(seg * 16));
        int gm = bm + row;
        bool am = active && (gm < M);
        size_t aoff = am ? ((size_t)gm * K + k0 + seg * 8) : 0;
        cp_async16(sb + SB_AH + so, Ah + aoff, am);
    }
#pragma unroll
    for (int t = 0; t < 2; t++) {
        int idx = t * 256 + tid;
        int row = idx >> 3, seg = idx & 7;
        uint32_t so = swz((uint32_t)row, (uint32_t)(seg * 16));
        size_t boff = (size_t)(bn + row) * K + k0 + seg * 8;
        cp_async16(sb + SB_BH + so, Bh + boff, active);
    }
}

__global__ void __launch_bounds__(256, 3)
mma_gemm_kernel(const __half* __restrict__ Ah, const __half* __restrict__ Bh,
                const float* __restrict__ bias1, const float* __restrict__ bias2,
                float* __restrict__ C, float* __restrict__ C2,
                __half* __restrict__ Chi,
                int M, int N1, int K, int relu)
{
    const uint32_t s0 = smem_to_u32(dyn_smem);
    const int tid  = threadIdx.x;
    const int wid  = tid >> 5;
    const int lane = tid & 31;
    const int wm   = wid & 3;
    const int wn   = wid >> 2;
    const int bm = blockIdx.y * 128;
    const int bn = blockIdx.x * 64;
    const int Ntot = gridDim.x * 64;

    float acc[2][4][4];
#pragma unroll
    for (int i = 0; i < 2; i++)
#pragma unroll
        for (int j = 0; j < 4; j++)
#pragma unroll
            for (int c = 0; c < 4; c++) acc[i][j][c] = 0.f;

    const int nch = K >> 6;

#pragma unroll
    for (int s = 0; s < 3; s++) {
        gemm_issue_stage(s0 + s * STG_BYTES, Ah, Bh, bm, bn, s << 6, M, K, tid, s < nch);
        CP_COMMIT();
    }

    // hoisted per-thread fragment coordinates
    const uint32_t rA_base  = (uint32_t)(wm * 32 + (lane & 15));
    const uint32_t kbA_base = (uint32_t)((lane >> 4) << 4);
    const uint32_t rB_base  = (uint32_t)(wn * 32 + (lane & 7) + ((lane >> 4) << 3));
    const uint32_t kbB_base = (uint32_t)(((lane >> 3) & 1) << 4);

    for (int ch = 0; ch < nch; ch++) {
        CP_WAIT2();
        __syncthreads();
        const uint32_t sb = s0 + (ch % 3) * STG_BYTES;
        const uint32_t sAH = sb + SB_AH, sBH = sb + SB_BH;

#pragma unroll
        for (int ks = 0; ks < 4; ks++) {
            uint32_t a_h[2][4];
#pragma unroll
            for (int mt = 0; mt < 2; mt++) {
                uint32_t off = swz(rA_base + mt * 16, ks * 32 + kbA_base);
                LDSM_X4(a_h[mt], sAH + off);
            }
            uint32_t b_h[4][2];
#pragma unroll
            for (int np = 0; np < 2; np++) {
                uint32_t off = swz(rB_base + np * 16, ks * 32 + kbB_base);
                uint32_t r4[4];
                LDSM_X4(r4, sBH + off);
                b_h[np * 2][0] = r4[0]; b_h[np * 2][1] = r4[1];
                b_h[np * 2 + 1][0] = r4[2]; b_h[np * 2 + 1][1] = r4[3];
            }
#pragma unroll
            for (int mt = 0; mt < 2; mt++)
#pragma unroll
                for (int nt = 0; nt < 4; nt++)
                    MMA_F16(acc[mt][nt], a_h[mt], b_h[nt]);
        }
        __syncthreads();
        int nxt = ch + 3;
        gemm_issue_stage(s0 + (nxt % 3) * STG_BYTES, Ah, Bh,
                         bm, bn, nxt << 6, M, K, tid, nxt < nch);
        CP_COMMIT();
    }

    // epilogue
    const int mrow0 = bm + wm * 32;
    const int ncol0 = bn + wn * 32;
#pragma unroll
    for (int mt = 0; mt < 2; mt++) {
        int r0 = mrow0 + mt * 16 + (lane >> 2);
        int r1 = r0 + 8;
#pragma unroll
        for (int nt = 0; nt < 4; nt++) {
            int n = ncol0 + nt * 8 + (lane & 3) * 2;
            float* dst; int stride; int nc;
            float bi0, bi1;
            if (C2 && n >= N1) {
                nc = n - N1; dst = C2; stride = Ntot - N1;
                bi0 = __ldg(&bias2[nc]); bi1 = __ldg(&bias2[nc + 1]);
            } else {
                nc = n; dst = C; stride = N1;
                bi0 = __ldg(&bias1[nc]); bi1 = __ldg(&bias1[nc + 1]);
            }
            float v00 = acc[mt][nt][0] + bi0, v01 = acc[mt][nt][1] + bi1;
            float v10 = acc[mt][nt][2] + bi0, v11 = acc[mt][nt][3] + bi1;
            if (relu) {
                v00 = fmaxf(v00, 0.f); v01 = fmaxf(v01, 0.f);
                v10 = fmaxf(v10, 0.f); v11 = fmaxf(v11, 0.f);
            }
            if (C) {
                if (r0 < M) *(float2*)(dst + (size_t)r0 * stride + nc) = make_float2(v00, v01);
                if (r1 < M) *(float2*)(dst + (size_t)r1 * stride + nc) = make_float2(v10, v11);
            } else {
                if (r0 < M)
                    *(__half2*)(Chi + (size_t)r0 * Ntot + n) =
                        __halves2half2(__float2half(v00), __float2half(v01));
                if (r1 < M)
                    *(__half2*)(Chi + (size_t)r1 * Ntot + n) =
                        __halves2half2(__float2half(v10), __float2half(v11));
            }
        }
    }
}

// ---------------- prep: build q,v AND convert weights (merged) ----------------
__global__ void prep_kernel(const float* __restrict__ src,
                            const float* __restrict__ pos,
                            const float* __restrict__ sel_vt,
                            const float* __restrict__ Wv, const float* __restrict__ Wo,
                            const float* __restrict__ Wa, const float* __restrict__ Wout,
                            const float* __restrict__ W1, const float* __restrict__ W2)
{
    size_t idx = (size_t)blockIdx.x * blockDim.x + threadIdx.x;
    const size_t QV = (size_t)ROWS * DM;
    if (idx < QV) {
        size_t row = idx / DM;
        int d = (int)(idx % DM);
        int n = (int)(row / LQ);
        int r = (int)(row % LQ);
        float qv, vv;
        if (r < L_SP) {
            size_t si = ((size_t)n * L_SP + r) * DM + d;
            float s = src[si];
            qv = s + pos[si];
            vv = s;
        } else {
            size_t si = ((size_t)n * N_VT + (r - L_SP)) * DM + d;
            float s = sel_vt[si];
            qv = s; vv = s;
        }
        g_v[idx] = vv;
        g_qh[idx] = __float2half(qv);
        g_vh[idx] = __float2half(vv);
    } else {
        size_t i = idx - QV;
        if (i >= WTOT) return;
        float x;
        if      (i < WOFF_O)   x = Wv  [i];
        else if (i < WOFF_A)   x = Wo  [i - WOFF_O];
        else if (i < WOFF_OUT) x = Wa  [i - WOFF_A];
        else if (i < WOFF_1)   x = Wout[i - WOFF_OUT];
        else if (i < WOFF_2)   x = W1  [i - WOFF_1];
        else                   x = W2  [i - WOFF_2];
        g_wh[i] = __float2half(x);
    }
}

// ---------------- deformable sampling + fused softmax (full load hoist) ----------------
// block = row, warp = head. Lanes 0-15: dims [0,32) as half2 for point 2*pp;
// lanes 16-31: same dims, point 2*pp+1. Phase 1 computes all 8 iterations'
// coefficients+indices; phase 2 issues all 32 gathers (MLP~32); phase 3 accumulates.
__global__ void __launch_bounds__(256) sample_kernel(const float* __restrict__ ref)
{
    const int row = blockIdx.x;
    const int m    = threadIdx.x >> 5;
    const int lane = threadIdx.x & 31;
    const int psel = lane >> 4;
    const int dp   = lane & 15;
    const int n    = row / LQ;

    const float* refp = ref + (size_t)row * (NLEV * 2);
    const float* offp = g_off + (size_t)row * DM + m * (NLEV * NPTS * 2);
    const float* attp = g_attn + (size_t)row * 128 + m * 16;
    const __half2* valn = (const __half2*)(g_valh + (size_t)n * LQ * DM);
    const int hoff = m * (DH / 2) + dp;

    // fused softmax over this head's 16 logits
    float a16[16];
    float mx = -1e30f;
#pragma unroll
    for (int i = 0; i < 16; i++) { a16[i] = __ldg(&attp[i]); mx = fmaxf(mx, a16[i]); }
    float ssum = 0.f;
#pragma unroll
    for (int i = 0; i < 16; i++) { a16[i] = __expf(a16[i] - mx); ssum += a16[i]; }
    const float sinv = 1.f / ssum;

    // phase 1: coefficients + gather indices for all 8 (level, pp) iterations
    int   gi[8][4];
    float gc[8][4];
#pragma unroll
    for (int l = 0; l < NLEV; l++) {
        const int H = c_H[l], W = c_W[l], st = c_start[l];
        const float rx = refp[l * 2 + 0];
        const float ry = refp[l * 2 + 1];
#pragma unroll
        for (int pp = 0; pp < 2; pp++) {
            const int it = l * 2 + pp;
            const int p = pp * 2 + psel;
            const float ox = offp[(l * NPTS + p) * 2 + 0];
            const float oy = offp[(l * NPTS + p) * 2 + 1];
            const float a  = a16[l * NPTS + p] * sinv;
            const float x = rx * W + ox - 0.5f;
            const float y = ry * H + oy - 0.5f;
            const float x0f = floorf(x), y0f = floorf(y);
            const float wx = x - x0f, wy = y - y0f;
            const int x0 = (int)x0f, y0 = (int)y0f;
            const int x1 = x0 + 1,   y1 = y0 + 1;
            const float vx0 = (x0 >= 0 && x0 < W) ? 1.f : 0.f;
            const float vx1 = (x1 >= 0 && x1 < W) ? 1.f : 0.f;
            const float vy0 = (y0 >= 0 && y0 < H) ? 1.f : 0.f;
            const float vy1 = (y1 >= 0 && y1 < H) ? 1.f : 0.f;
            const int x0c = min(max(x0, 0), W - 1), x1c = min(max(x1, 0), W - 1);
            const int y0c = min(max(y0, 0), H - 1), y1c = min(max(y1, 0), H - 1);
            gc[it][0] = a * (1.f - wx) * (1.f - wy) * vx0 * vy0;
            gc[it][1] = a * wx * (1.f - wy) * vx1 * vy0;
            gc[it][2] = a * (1.f - wx) * wy * vx0 * vy1;
            gc[it][3] = a * wx * wy * vx1 * vy1;
            const int rb0 = st + y0c * W, rb1 = st + y1c * W;
            gi[it][0] = (rb0 + x0c) * (DM / 2) + hoff;
            gi[it][1] = (rb0 + x1c) * (DM / 2) + hoff;
            gi[it][2] = (rb1 + x0c) * (DM / 2) + hoff;
            gi[it][3] = (rb1 + x1c) * (DM / 2) + hoff;
        }
    }
    // phase 2: all 32 gathers issued back-to-back
    __half2 gv[8][4];
#pragma unroll
    for (int it = 0; it < 8; it++)
#pragma unroll
        for (int k = 0; k < 4; k++)
            gv[it][k] = valn[(size_t)(uint32_t)gi[it][k]];
    // phase 3: accumulate
    float accx = 0.f, accy = 0.f;
#pragma unroll
    for (int it = 0; it < 8; it++)
#pragma unroll
        for (int k = 0; k < 4; k++) {
            float2 f = __half22float2(gv[it][k]);
            accx = fmaf(gc[it][k], f.x, accx);
            accy = fmaf(gc[it][k], f.y, accy);
        }

    accx += __shfl_xor_sync(0xffffffffu, accx, 16);
    accy += __shfl_xor_sync(0xffffffffu, accy, 16);
    if (psel == 0) {
        __half2* dst = (__half2*)(g_sh + (size_t)row * DM + m * DH) + dp;
        *dst = __halves2half2(__float2half(accx), __float2half(accy));
    }
}

// ---------------- residual + LayerNorm (+ optional fp16 out) ----------------
__global__ void resid_ln_kernel(const float* __restrict__ a,
                                const float* __restrict__ b,
                                const float* __restrict__ g,
                                const float* __restrict__ beta,
                                float* __restrict__ out,
                                __half* __restrict__ outH)
{
    __shared__ float red[64];
    const int row = blockIdx.x;
    const int t = threadIdx.x;
    size_t base = (size_t)row * DM;
    float x = a[base + t] + b[base + t];

    float s = x;
#pragma unroll
    for (int o = 16; o > 0; o >>= 1) s += __shfl_xor_sync(0xffffffffu, s, o);
    if ((t & 31) == 0) red[t >> 5] = s;
    __syncthreads();
    if (t < 8) {
        float v = red[t];
#pragma unroll
        for (int o = 4; o > 0; o >>= 1) v += __shfl_xor_sync(0xffu, v, o);
        if (t == 0) red[32] = v;
    }
    __syncthreads();
    float mean = red[32] * (1.f / DM);

    float xc = x - mean;
    float sq = xc * xc;
#pragma unroll
    for (int o = 16; o > 0; o >>= 1) sq += __shfl_xor_sync(0xffffffffu, sq, o);
    if ((t & 31) == 0) red[t >> 5] = sq;
    __syncthreads();
    if (t < 8) {
        float v = red[t];
#pragma unroll
        for (int o = 4; o > 0; o >>= 1) v += __shfl_xor_sync(0xffu, v, o);
        if (t == 0) red[33] = v;
    }
    __syncthreads();
    float var = red[33] * (1.f / DM);
    float inv = rsqrtf(var + EPSLN);
    float y = g[t] * xc * inv + beta[t];
    out[base + t] = y;
    if (outH) outH[base + t] = __float2half(y);
}

// ---------------- final residual + LayerNorm writing straight to d_out ----------------
__global__ void resid_ln_out_kernel(const float* __restrict__ a,
                                    const float* __restrict__ b,
                                    const float* __restrict__ g,
                                    const float* __restrict__ beta,
                                    float* __restrict__ out)
{
    __shared__ float red[64];
    const int row = blockIdx.x;
    const int t = threadIdx.x;
    size_t base = (size_t)row * DM;
    float x = a[base + t] + b[base + t];

    float s = x;
#pragma unroll
    for (int o = 16; o > 0; o >>= 1) s += __shfl_xor_sync(0xffffffffu, s, o);
    if ((t & 31) == 0) red[t >> 5] = s;
    __syncthreads();
    if (t < 8) {
        float v = red[t];
#pragma unroll
        for (int o = 4; o > 0; o >>= 1) v += __shfl_xor_sync(0xffu, v, o);
        if (t == 0) red[32] = v;
    }
    __syncthreads();
    float mean = red[32] * (1.f / DM);

    float xc = x - mean;
    float sq = xc * xc;
#pragma unroll
    for (int o = 16; o > 0; o >>= 1) sq += __shfl_xor_sync(0xffffffffu, sq, o);
    if ((t & 31) == 0) red[t >> 5] = sq;
    __syncthreads();
    if (t < 8) {
        float v = red[t];
#pragma unroll
        for (int o = 4; o > 0; o >>= 1) v += __shfl_xor_sync(0xffu, v, o);
        if (t == 0) red[33] = v;
    }
    __syncthreads();
    float var = red[33] * (1.f / DM);
    float inv = rsqrtf(var + EPSLN);
    float y = g[t] * xc * inv + beta[t];

    const int n = row / LQ, r = row % LQ;
    const size_t P1 = (size_t)NB * L_SP * DM;
    const size_t P2 = (size_t)NB * 75 * N_VT * DM;
    size_t oidx;
    if (r < L_SP) oidx = ((size_t)n * L_SP + r) * DM + t;
    else          oidx = P1 + P2 + ((size_t)n * N_VT + (r - L_SP)) * DM + t;
    out[oidx] = y;
}

// ---------------- all_vt passthrough copy ----------------
__global__ void copy_vt_kernel(const float* __restrict__ all_vt, float* __restrict__ out)
{
    const size_t P1 = (size_t)NB * L_SP * DM;
    const size_t P2 = (size_t)NB * 75 * N_VT * DM;
    size_t idx = (size_t)blockIdx.x * blockDim.x + threadIdx.x;
    if (idx < P2) out[P1 + idx] = all_vt[idx];
}

// ---------------- launch ----------------
extern "C" void kernel_launch(void* const* d_in, const int* in_sizes, int n_in,
                              void* d_out, int out_size)
{
    const float* src     = (const float*)d_in[0];
    const float* pos     = (const float*)d_in[1];
    const float* refpts  = (const float*)d_in[2];
    const float* all_vt  = (const float*)d_in[6];
    const float* sel_vt  = (const float*)d_in[7];
    const float* W_value = (const float*)d_in[8];
    const float* b_value = (const float*)d_in[9];
    const float* W_off   = (const float*)d_in[10];
    const float* b_off   = (const float*)d_in[11];
    const float* W_attn  = (const float*)d_in[12];
    const float* b_attn  = (const float*)d_in[13];
    const float* W_out   = (const float*)d_in[14];
    const float* b_out   = (const float*)d_in[15];
    const float* g1      = (const float*)d_in[16];
    const float* beta1   = (const float*)d_in[17];
    const float* W1      = (const float*)d_in[18];
    const float* bf1     = (const float*)d_in[19];
    const float* W2      = (const float*)d_in[20];
    const float* bf2     = (const float*)d_in[21];
    const float* g2      = (const float*)d_in[22];
    const float* beta2   = (const float*)d_in[23];
    float* out = (float*)d_out;

    float* p_v;    cudaGetSymbolAddress((void**)&p_v,    g_v);
    float* p_off;  cudaGetSymbolAddress((void**)&p_off,  g_off);
    float* p_attn; cudaGetSymbolAddress((void**)&p_attn, g_attn);
    float* p_tmp;  cudaGetSymbolAddress((void**)&p_tmp,  g_tmp);
    float* p_x;    cudaGetSymbolAddress((void**)&p_x,    g_x);
    __half *p_valh, *p_qh, *p_vh, *p_sh, *p_xh, *p_h1h, *p_wh;
    cudaGetSymbolAddress((void**)&p_valh, g_valh);
    cudaGetSymbolAddress((void**)&p_qh,  g_qh);
    cudaGetSymbolAddress((void**)&p_vh,  g_vh);
    cudaGetSymbolAddress((void**)&p_sh,  g_sh);
    cudaGetSymbolAddress((void**)&p_xh,  g_xh);
    cudaGetSymbolAddress((void**)&p_h1h, g_h1h);
    cudaGetSymbolAddress((void**)&p_wh,  g_wh);

    static int smem_set = 0;
    if (!smem_set) {
        cudaFuncSetAttribute(mma_gemm_kernel, cudaFuncAttributeMaxDynamicSharedMemorySize, GSM_TOTAL);
        smem_set = 1;
    }

    const int M = ROWS;
    const int MT = (M + 127) / 128;   // 171

    // 1. prep: build q/v + weight conversion (merged)
    {
        size_t total = (size_t)ROWS * DM + WTOT;
        prep_kernel<<<(unsigned)((total + 255) / 256), 256>>>(src, pos, sel_vt,
            W_value, W_off, W_attn, W_out, W1, W2);
    }
    // 2. value projection -> fp16 (sampling source)
    mma_gemm_kernel<<<dim3(4, MT), 256, GSM_TOTAL>>>(p_vh, p_wh + WOFF_V,
        b_value, nullptr, nullptr, nullptr, p_valh, M, DM, DM, 0);
    // 3. fused offsets+attn: B = [Wo; Wa], N=384; cols<256 -> g_off, cols>=256 -> g_attn (raw)
    mma_gemm_kernel<<<dim3(6, MT), 256, GSM_TOTAL>>>(p_qh, p_wh + WOFF_O,
        b_off, b_attn, p_off, p_attn, nullptr, M, DM, DM, 0);
    // 4. deformable sampling (softmax fused) -> fp16
    sample_kernel<<<ROWS, 256>>>(refpts);
    // 5. output projection -> g_tmp
    mma_gemm_kernel<<<dim3(4, MT), 256, GSM_TOTAL>>>(p_sh, p_wh + WOFF_OUT,
        b_out, nullptr, p_tmp, nullptr, nullptr, M, DM, DM, 0);
    // 6. x = LN(v + src2) (+ fp16)
    resid_ln_kernel<<<ROWS, 256>>>(p_v, p_tmp, g1, beta1, p_x, p_xh);
    // 7. h1 = relu(x @ W1^T + bf1) -> fp16 (N=1024)
    mma_gemm_kernel<<<dim3(16, MT), 256, GSM_TOTAL>>>(p_xh, p_wh + WOFF_1,
        bf1, nullptr, nullptr, nullptr, p_h1h, M, DF, DM, 1);
    // 8. h = h1 @ W2^T + bf2 -> g_tmp (K=1024)
    mma_gemm_kernel<<<dim3(4, MT), 256, GSM_TOTAL>>>(p_h1h, p_wh + WOFF_2,
        bf2, nullptr, p_tmp, nullptr, nullptr, M, DM, DF, 0);
    // 9. x = LN(x + h) -> directly into d_out (mapped)
    resid_ln_out_kernel<<<ROWS, 256>>>(p_x, p_tmp, g2, beta2, out);
    // 10. all_vt passthrough
    {
        size_t total = (size_t)NB * 75 * N_VT * DM;
        copy_vt_kernel<<<(unsigned)((total + 255) / 256), 256>>>(all_vt, out);
    }
}

// round 14
// speedup vs baseline: 1.3564x; 1.3564x over previous
#include <cuda_runtime.h>
#include <cuda_fp16.h>
#include <math.h>
#include <cstdint>

// ---------------- problem constants ----------------
#define NB     4
#define L_SP   5440
#define N_VT   8
#define LQ     (L_SP + N_VT)      // 5448
#define DM     256
#define DF     1024
#define NH     8
#define DH     32
#define NLEV   4
#define NPTS   4
#define ROWS   (NB * LQ)          // 21792
#define EPSLN  1e-5f

// ---------------- scratch (device globals; no allocs) ----------------
static __device__ float g_v   [ (size_t)ROWS * DM ];   // v_in fp32 (residual 1)
static __device__ float g_off [ (size_t)ROWS * DM ];
static __device__ float g_attn[ (size_t)ROWS * 128 ];  // raw logits (softmax fused in sample)
static __device__ float g_tmp [ (size_t)ROWS * DM ];
static __device__ float g_x   [ (size_t)ROWS * DM ];

static __device__ __half g_valh[ (size_t)ROWS * DM ];  // value projection (sampling source)
static __device__ __half g_qh [ (size_t)ROWS * DM ];
static __device__ __half g_vh [ (size_t)ROWS * DM ];
static __device__ __half g_sh [ (size_t)ROWS * DM ];
static __device__ __half g_xh [ (size_t)ROWS * DM ];
static __device__ __half g_h1h[ (size_t)ROWS * DF ];

// weights (concatenated fp16): Wv | Wo | Wa | Wout | W1 | W2
#define WOFF_V    0
#define WOFF_O    65536
#define WOFF_A    131072
#define WOFF_OUT  163840
#define WOFF_1    229376
#define WOFF_2    491520
#define WTOT      753664
static __device__ __half g_wh[WTOT];

// ---------------- helpers ----------------
__device__ __forceinline__ uint32_t smem_to_u32(const void* p) {
    uint32_t a;
    asm("{ .reg .u64 t; cvta.to.shared.u64 t, %1; cvt.u32.u64 %0, t; }" : "=r"(a) : "l"(p));
    return a;
}

#define LDSM_X4(r, addr) \
    asm volatile("ldmatrix.sync.aligned.m8n8.x4.shared.b16 {%0,%1,%2,%3}, [%4];" \
        : "=r"((r)[0]), "=r"((r)[1]), "=r"((r)[2]), "=r"((r)[3]) : "r"(addr))

#define MMA_F16(d, a, b) \
    asm volatile("mma.sync.aligned.m16n8k16.row.col.f32.f16.f16.f32 " \
        "{%0,%1,%2,%3}, {%4,%5,%6,%7}, {%8,%9}, {%0,%1,%2,%3};" \
        : "+f"((d)[0]), "+f"((d)[1]), "+f"((d)[2]), "+f"((d)[3]) \
        : "r"((a)[0]), "r"((a)[1]), "r"((a)[2]), "r"((a)[3]), \
          "r"((b)[0]), "r"((b)[1]))

__device__ __forceinline__ void cp_async16(uint32_t dst, const void* src, bool pred) {
    int sz = pred ? 16 : 0;
    asm volatile("cp.async.cg.shared.global [%0], [%1], 16, %2;"
        :: "r"(dst), "l"(src), "r"(sz) : "memory");
}
#define CP_COMMIT() asm volatile("cp.async.commit_group;" ::: "memory")
#define CP_WAIT1()  asm volatile("cp.async.wait_group 1;" ::: "memory")

// swizzled byte offset within rows of 128 bytes
__device__ __forceinline__ uint32_t swz(uint32_t row, uint32_t kb) {
    return row * 128u + (kb ^ ((row & 7u) << 4));
}

// ---------------- pipelined warp-MMA 1-term fp16 GEMM (R9 known-good config) ----------------
// C = Ah @ Bh^T + bias. CTA tile 128x64, BK=64, 256 threads (8 warps, 4m x 2n),
// warp tile 32x32. 2-stage cp.async; stage = 24KB (AH 16K, BH 8K). 3 CTAs/SM.
#define STG_BYTES 24576
#define SB_AH 0
#define SB_BH 16384
#define GSM_TOTAL (2 * STG_BYTES)   // 49152

extern __shared__ char dyn_smem[];

__device__ __forceinline__ void gemm_issue_stage(
    uint32_t sb, const __half* Ah, const __half* Bh,
    int bm, int bn, int k0, int M, int K, int tid, bool active)
{
#pragma unroll
    for (int t = 0; t < 4; t++) {
        int idx = t * 256 + tid;
        int row = idx >> 3, seg = idx & 7;
        uint32_t so = swz((uint32_t)row, (uint32_t)(seg * 16));
        int gm = bm + row;
        bool am = active && (gm < M);
        size_t aoff = am ? ((size_t)gm * K + k0 + seg * 8) : 0;
        cp_async16(sb + SB_AH + so, Ah + aoff, am);
    }
#pragma unroll
    for (int t = 0; t < 2; t++) {
        int idx = t * 256 + tid;
        int row = idx >> 3, seg = idx & 7;
        uint32_t so = swz((uint32_t)row, (uint32_t)(seg * 16));
        size_t boff = (size_t)(bn + row) * K + k0 + seg * 8;
        cp_async16(sb + SB_BH + so, Bh + boff, active);
    }
}

__global__ void __launch_bounds__(256, 3)
mma_gemm_kernel(const __half* __restrict__ Ah, const __half* __restrict__ Bh,
                const float* __restrict__ bias1, const float* __restrict__ bias2,
                float* __restrict__ C, float* __restrict__ C2,
                __half* __restrict__ Chi,
                int M, int N1, int K, int relu)
{
    const uint32_t s0 = smem_to_u32(dyn_smem);
    const int tid  = threadIdx.x;
    const int wid  = tid >> 5;
    const int lane = tid & 31;
    const int wm   = wid & 3;
    const int wn   = wid >> 2;
    const int bm = blockIdx.y * 128;
    const int bn = blockIdx.x * 64;
    const int Ntot = gridDim.x * 64;

    float acc[2][4][4];
#pragma unroll
    for (int i = 0; i < 2; i++)
#pragma unroll
        for (int j = 0; j < 4; j++)
#pragma unroll
            for (int c = 0; c < 4; c++) acc[i][j][c] = 0.f;

    const int nch = K >> 6;

#pragma unroll
    for (int s = 0; s < 2; s++) {
        gemm_issue_stage(s0 + s * STG_BYTES, Ah, Bh, bm, bn, s << 6, M, K, tid, s < nch);
        CP_COMMIT();
    }

    const uint32_t rA_base  = (uint32_t)(wm * 32 + (lane & 15));
    const uint32_t kbA_base = (uint32_t)((lane >> 4) << 4);
    const uint32_t rB_base  = (uint32_t)(wn * 32 + (lane & 7) + ((lane >> 4) << 3));
    const uint32_t kbB_base = (uint32_t)(((lane >> 3) & 1) << 4);

    for (int ch = 0; ch < nch; ch++) {
        CP_WAIT1();
        __syncthreads();
        const uint32_t sb = s0 + (ch & 1) * STG_BYTES;
        const uint32_t sAH = sb + SB_AH, sBH = sb + SB_BH;

#pragma unroll
        for (int ks = 0; ks < 4; ks++) {
            uint32_t a_h[2][4];
#pragma unroll
            for (int mt = 0; mt < 2; mt++) {
                uint32_t off = swz(rA_base + mt * 16, ks * 32 + kbA_base);
                LDSM_X4(a_h[mt], sAH + off);
            }
            uint32_t b_h[4][2];
#pragma unroll
            for (int np = 0; np < 2; np++) {
                uint32_t off = swz(rB_base + np * 16, ks * 32 + kbB_base);
                uint32_t r4[4];
                LDSM_X4(r4, sBH + off);
                b_h[np * 2][0] = r4[0]; b_h[np * 2][1] = r4[1];
                b_h[np * 2 + 1][0] = r4[2]; b_h[np * 2 + 1][1] = r4[3];
            }
#pragma unroll
            for (int mt = 0; mt < 2; mt++)
#pragma unroll
                for (int nt = 0; nt < 4; nt++)
                    MMA_F16(acc[mt][nt], a_h[mt], b_h[nt]);
        }
        __syncthreads();
        int nxt = ch + 2;
        gemm_issue_stage(s0 + (nxt & 1) * STG_BYTES, Ah, Bh,
                         bm, bn, nxt << 6, M, K, tid, nxt < nch);
        CP_COMMIT();
    }

    // epilogue
    const int mrow0 = bm + wm * 32;
    const int ncol0 = bn + wn * 32;
#pragma unroll
    for (int mt = 0; mt < 2; mt++) {
        int r0 = mrow0 + mt * 16 + (lane >> 2);
        int r1 = r0 + 8;
#pragma unroll
        for (int nt = 0; nt < 4; nt++) {
            int n = ncol0 + nt * 8 + (lane & 3) * 2;
            float* dst; int stride; int nc;
            float bi0, bi1;
            if (C2 && n >= N1) {
                nc = n - N1; dst = C2; stride = Ntot - N1;
                bi0 = __ldg(&bias2[nc]); bi1 = __ldg(&bias2[nc + 1]);
            } else {
                nc = n; dst = C; stride = N1;
                bi0 = __ldg(&bias1[nc]); bi1 = __ldg(&bias1[nc + 1]);
            }
            float v00 = acc[mt][nt][0] + bi0, v01 = acc[mt][nt][1] + bi1;
            float v10 = acc[mt][nt][2] + bi0, v11 = acc[mt][nt][3] + bi1;
            if (relu) {
                v00 = fmaxf(v00, 0.f); v01 = fmaxf(v01, 0.f);
                v10 = fmaxf(v10, 0.f); v11 = fmaxf(v11, 0.f);
            }
            if (C) {
                if (r0 < M) *(float2*)(dst + (size_t)r0 * stride + nc) = make_float2(v00, v01);
                if (r1 < M) *(float2*)(dst + (size_t)r1 * stride + nc) = make_float2(v10, v11);
            } else {
                if (r0 < M)
                    *(__half2*)(Chi + (size_t)r0 * Ntot + n) =
                        __halves2half2(__float2half(v00), __float2half(v01));
                if (r1 < M)
                    *(__half2*)(Chi + (size_t)r1 * Ntot + n) =
                        __halves2half2(__float2half(v10), __float2half(v11));
            }
        }
    }
}

// ---------------- prep: build q,v AND convert weights (merged) ----------------
__global__ void prep_kernel(const float* __restrict__ src,
                            const float* __restrict__ pos,
                            const float* __restrict__ sel_vt,
                            const float* __restrict__ Wv, const float* __restrict__ Wo,
                            const float* __restrict__ Wa, const float* __restrict__ Wout,
                            const float* __restrict__ W1, const float* __restrict__ W2)
{
    size_t idx = (size_t)blockIdx.x * blockDim.x + threadIdx.x;
    const size_t QV = (size_t)ROWS * DM;
    if (idx < QV) {
        size_t row = idx / DM;
        int d = (int)(idx % DM);
        int n = (int)(row / LQ);
        int r = (int)(row % LQ);
        float qv, vv;
        if (r < L_SP) {
            size_t si = ((size_t)n * L_SP + r) * DM + d;
            float s = src[si];
            qv = s + pos[si];
            vv = s;
        } else {
            size_t si = ((size_t)n * N_VT + (r - L_SP)) * DM + d;
            float s = sel_vt[si];
            qv = s; vv = s;
        }
        g_v[idx] = vv;
        g_qh[idx] = __float2half(qv);
        g_vh[idx] = __float2half(vv);
    } else {
        size_t i = idx - QV;
        if (i >= WTOT) return;
        float x;
        if      (i < WOFF_O)   x = Wv  [i];
        else if (i < WOFF_A)   x = Wo  [i - WOFF_O];
        else if (i < WOFF_OUT) x = Wa  [i - WOFF_A];
        else if (i < WOFF_1)   x = Wout[i - WOFF_OUT];
        else if (i < WOFF_2)   x = W1  [i - WOFF_1];
        else                   x = W2  [i - WOFF_2];
        g_wh[i] = __float2half(x);
    }
}

// ---------------- deformable sampling + fused softmax (issue-optimized) ----------------
// block = row, warp = head. 4 lanes per point (int4 = 8 halves of the head dim),
// psel = lane>>2 in 0..7 selects the point; two iterations cover 16 points.
// Softmax distributed: lane computes exp of logit (lane&15); butterfly reduce;
// per-point weight fetched via shfl. Coefficients computed 4x-redundant (vs 16x).
__global__ void __launch_bounds__(256) sample_kernel(const float* __restrict__ ref)
{
    const int row = blockIdx.x;
    const int m    = threadIdx.x >> 5;   // head
    const int lane = threadIdx.x & 31;
    const int psel = lane >> 2;          // 0..7 point slot
    const int d4   = lane & 3;           // int4 slot within head (8 dims)
    const int n    = row / LQ;

    const float* refp = ref + (size_t)row * (NLEV * 2);
    const float* offp = g_off + (size_t)row * DM + m * 32;
    const float* attp = g_attn + (size_t)row * 128 + m * 16;
    const int4* valn = (const int4*)(g_valh + (size_t)n * LQ * DM);  // 32 int4 per row
    const int hoff = m * 4 + d4;

    // distributed softmax over 16 logits
    float lg = __ldg(&attp[lane & 15]);
    float mx = lg;
#pragma unroll
    for (int o = 8; o > 0; o >>= 1) mx = fmaxf(mx, __shfl_xor_sync(0xffffffffu, mx, o));
    float e = __expf(lg - mx);
    float ssum = e;
#pragma unroll
    for (int o = 8; o > 0; o >>= 1) ssum += __shfl_xor_sync(0xffffffffu, ssum, o);
    const float sinv = 1.f / ssum;

    // phase 1: coefficients + indices for this lane's 2 points
    float gc[2][4];
    int   gi[2][4];
#pragma unroll
    for (int it = 0; it < 2; it++) {
        const int p = it * 8 + psel;           // global point 0..15
        const int l = p >> 2;                  // level
        const int W = 64 >> l;                 // H == W
        const int st = (16384 - (16384 >> (2 * l))) / 3;
        const float a = __shfl_sync(0xffffffffu, e, p) * sinv;
        const float rx = refp[l * 2 + 0];
        const float ry = refp[l * 2 + 1];
        const float ox = offp[p * 2 + 0];
        const float oy = offp[p * 2 + 1];
        const float x = rx * W + ox - 0.5f;
        const float y = ry * W + oy - 0.5f;
        const float x0f = floorf(x), y0f = floorf(y);
        const float wx = x - x0f, wy = y - y0f;
        const int x0 = (int)x0f, y0 = (int)y0f;
        const int x1 = x0 + 1,   y1 = y0 + 1;
        const float vx0 = (x0 >= 0 && x0 < W) ? 1.f : 0.f;
        const float vx1 = (x1 >= 0 && x1 < W) ? 1.f : 0.f;
        const float vy0 = (y0 >= 0 && y0 < W) ? 1.f : 0.f;
        const float vy1 = (y1 >= 0 && y1 < W) ? 1.f : 0.f;
        const int x0c = min(max(x0, 0), W - 1), x1c = min(max(x1, 0), W - 1);
        const int y0c = min(max(y0, 0), W - 1), y1c = min(max(y1, 0), W - 1);
        gc[it][0] = a * (1.f - wx) * (1.f - wy) * vx0 * vy0;
        gc[it][1] = a * wx * (1.f - wy) * vx1 * vy0;
        gc[it][2] = a * (1.f - wx) * wy * vx0 * vy1;
        gc[it][3] = a * wx * wy * vx1 * vy1;
        const int rb0 = st + y0c * W, rb1 = st + y1c * W;
        gi[it][0] = (rb0 + x0c) * 32 + hoff;
        gi[it][1] = (rb0 + x1c) * 32 + hoff;
        gi[it][2] = (rb1 + x0c) * 32 + hoff;
        gi[it][3] = (rb1 + x1c) * 32 + hoff;
    }
    // phase 2: 8 int4 gathers back-to-back
    int4 gv[2][4];
#pragma unroll
    for (int it = 0; it < 2; it++)
#pragma unroll
        for (int k = 0; k < 4; k++)
            gv[it][k] = valn[(size_t)(uint32_t)gi[it][k]];
    // phase 3: accumulate 8 dims
    float acc[8];
#pragma unroll
    for (int j = 0; j < 8; j++) acc[j] = 0.f;
#pragma unroll
    for (int it = 0; it < 2; it++)
#pragma unroll
        for (int k = 0; k < 4; k++) {
            const float c = gc[it][k];
            const __half2* h2 = (const __half2*)&gv[it][k];
#pragma unroll
            for (int q = 0; q < 4; q++) {
                float2 f = __half22float2(h2[q]);
                acc[q * 2 + 0] = fmaf(c, f.x, acc[q * 2 + 0]);
                acc[q * 2 + 1] = fmaf(c, f.y, acc[q * 2 + 1]);
            }
        }
    // reduce across 8 point-slots (psel): xor 4, 8, 16
#pragma unroll
    for (int o = 4; o <= 16; o <<= 1)
#pragma unroll
        for (int j = 0; j < 8; j++)
            acc[j] += __shfl_xor_sync(0xffffffffu, acc[j], o);

    if (psel == 0) {
        __half2 hout[4];
#pragma unroll
        for (int q = 0; q < 4; q++)
            hout[q] = __halves2half2(__float2half(acc[q * 2]), __float2half(acc[q * 2 + 1]));
        int4* dst = (int4*)(g_sh + (size_t)row * DM + m * DH) + d4;
        *dst = *(int4*)hout;
    }
}

// ---------------- residual + LayerNorm (+ optional fp16 out) ----------------
__global__ void resid_ln_kernel(const float* __restrict__ a,
                                const float* __restrict__ b,
                                const float* __restrict__ g,
                                const float* __restrict__ beta,
                                float* __restrict__ out,
                                __half* __restrict__ outH)
{
    __shared__ float red[64];
    const int row = blockIdx.x;
    const int t = threadIdx.x;
    size_t base = (size_t)row * DM;
    float x = a[base + t] + b[base + t];

    float s = x;
#pragma unroll
    for (int o = 16; o > 0; o >>= 1) s += __shfl_xor_sync(0xffffffffu, s, o);
    if ((t & 31) == 0) red[t >> 5] = s;
    __syncthreads();
    if (t < 8) {
        float v = red[t];
#pragma unroll
        for (int o = 4; o > 0; o >>= 1) v += __shfl_xor_sync(0xffu, v, o);
        if (t == 0) red[32] = v;
    }
    __syncthreads();
    float mean = red[32] * (1.f / DM);

    float xc = x - mean;
    float sq = xc * xc;
#pragma unroll
    for (int o = 16; o > 0; o >>= 1) sq += __shfl_xor_sync(0xffffffffu, sq, o);
    if ((t & 31) == 0) red[t >> 5] = sq;
    __syncthreads();
    if (t < 8) {
        float v = red[t];
#pragma unroll
        for (int o = 4; o > 0; o >>= 1) v += __shfl_xor_sync(0xffu, v, o);
        if (t == 0) red[33] = v;
    }
    __syncthreads();
    float var = red[33] * (1.f / DM);
    float inv = rsqrtf(var + EPSLN);
    float y = g[t] * xc * inv + beta[t];
    out[base + t] = y;
    if (outH) outH[base + t] = __float2half(y);
}

// ---------------- final residual + LayerNorm writing straight to d_out ----------------
__global__ void resid_ln_out_kernel(const float* __restrict__ a,
                                    const float* __restrict__ b,
                                    const float* __restrict__ g,
                                    const float* __restrict__ beta,
                                    float* __restrict__ out)
{
    __shared__ float red[64];
    const int row = blockIdx.x;
    const int t = threadIdx.x;
    size_t base = (size_t)row * DM;
    float x = a[base + t] + b[base + t];

    float s = x;
#pragma unroll
    for (int o = 16; o > 0; o >>= 1) s += __shfl_xor_sync(0xffffffffu, s, o);
    if ((t & 31) == 0) red[t >> 5] = s;
    __syncthreads();
    if (t < 8) {
        float v = red[t];
#pragma unroll
        for (int o = 4; o > 0; o >>= 1) v += __shfl_xor_sync(0xffu, v, o);
        if (t == 0) red[32] = v;
    }
    __syncthreads();
    float mean = red[32] * (1.f / DM);

    float xc = x - mean;
    float sq = xc * xc;
#pragma unroll
    for (int o = 16; o > 0; o >>= 1) sq += __shfl_xor_sync(0xffffffffu, sq, o);
    if ((t & 31) == 0) red[t >> 5] = sq;
    __syncthreads();
    if (t < 8) {
        float v = red[t];
#pragma unroll
        for (int o = 4; o > 0; o >>= 1) v += __shfl_xor_sync(0xffu, v, o);
        if (t == 0) red[33] = v;
    }
    __syncthreads();
    float var = red[33] * (1.f / DM);
    float inv = rsqrtf(var + EPSLN);
    float y = g[t] * xc * inv + beta[t];

    const int n = row / LQ, r = row % LQ;
    const size_t P1 = (size_t)NB * L_SP * DM;
    const size_t P2 = (size_t)NB * 75 * N_VT * DM;
    size_t oidx;
    if (r < L_SP) oidx = ((size_t)n * L_SP + r) * DM + t;
    else          oidx = P1 + P2 + ((size_t)n * N_VT + (r - L_SP)) * DM + t;
    out[oidx] = y;
}

// ---------------- all_vt passthrough copy ----------------
__global__ void copy_vt_kernel(const float* __restrict__ all_vt, float* __restrict__ out)
{
    const size_t P1 = (size_t)NB * L_SP * DM;
    const size_t P2 = (size_t)NB * 75 * N_VT * DM;
    size_t idx = (size_t)blockIdx.x * blockDim.x + threadIdx.x;
    if (idx < P2) out[P1 + idx] = all_vt[idx];
}

// ---------------- launch ----------------
extern "C" void kernel_launch(void* const* d_in, const int* in_sizes, int n_in,
                              void* d_out, int out_size)
{
    const float* src     = (const float*)d_in[0];
    const float* pos     = (const float*)d_in[1];
    const float* refpts  = (const float*)d_in[2];
    const float* all_vt  = (const float*)d_in[6];
    const float* sel_vt  = (const float*)d_in[7];
    const float* W_value = (const float*)d_in[8];
    const float* b_value = (const float*)d_in[9];
    const float* W_off   = (const float*)d_in[10];
    const float* b_off   = (const float*)d_in[11];
    const float* W_attn  = (const float*)d_in[12];
    const float* b_attn  = (const float*)d_in[13];
    const float* W_out   = (const float*)d_in[14];
    const float* b_out   = (const float*)d_in[15];
    const float* g1      = (const float*)d_in[16];
    const float* beta1   = (const float*)d_in[17];
    const float* W1      = (const float*)d_in[18];
    const float* bf1     = (const float*)d_in[19];
    const float* W2      = (const float*)d_in[20];
    const float* bf2     = (const float*)d_in[21];
    const float* g2      = (const float*)d_in[22];
    const float* beta2   = (const float*)d_in[23];
    float* out = (float*)d_out;

    float* p_v;    cudaGetSymbolAddress((void**)&p_v,    g_v);
    float* p_off;  cudaGetSymbolAddress((void**)&p_off,  g_off);
    float* p_attn; cudaGetSymbolAddress((void**)&p_attn, g_attn);
    float* p_tmp;  cudaGetSymbolAddress((void**)&p_tmp,  g_tmp);
    float* p_x;    cudaGetSymbolAddress((void**)&p_x,    g_x);
    __half *p_valh, *p_qh, *p_vh, *p_sh, *p_xh, *p_h1h, *p_wh;
    cudaGetSymbolAddress((void**)&p_valh, g_valh);
    cudaGetSymbolAddress((void**)&p_qh,  g_qh);
    cudaGetSymbolAddress((void**)&p_vh,  g_vh);
    cudaGetSymbolAddress((void**)&p_sh,  g_sh);
    cudaGetSymbolAddress((void**)&p_xh,  g_xh);
    cudaGetSymbolAddress((void**)&p_h1h, g_h1h);
    cudaGetSymbolAddress((void**)&p_wh,  g_wh);

    static int smem_set = 0;
    if (!smem_set) {
        cudaFuncSetAttribute(mma_gemm_kernel, cudaFuncAttributeMaxDynamicSharedMemorySize, GSM_TOTAL);
        smem_set = 1;
    }

    const int M = ROWS;
    const int MT = (M + 127) / 128;   // 171

    // 1. prep: build q/v + weight conversion (merged)
    {
        size_t total = (size_t)ROWS * DM + WTOT;
        prep_kernel<<<(unsigned)((total + 255) / 256), 256>>>(src, pos, sel_vt,
            W_value, W_off, W_attn, W_out, W1, W2);
    }
    // 2. value projection -> fp16 (sampling source)
    mma_gemm_kernel<<<dim3(4, MT), 256, GSM_TOTAL>>>(p_vh, p_wh + WOFF_V,
        b_value, nullptr, nullptr, nullptr, p_valh, M, DM, DM, 0);
    // 3. fused offsets+attn: B = [Wo; Wa], N=384; cols<256 -> g_off, cols>=256 -> g_attn (raw)
    mma_gemm_kernel<<<dim3(6, MT), 256, GSM_TOTAL>>>(p_qh, p_wh + WOFF_O,
        b_off, b_attn, p_off, p_attn, nullptr, M, DM, DM, 0);
    // 4. deformable sampling (softmax fused) -> fp16
    sample_kernel<<<ROWS, 256>>>(refpts);
    // 5. output projection -> g_tmp
    mma_gemm_kernel<<<dim3(4, MT), 256, GSM_TOTAL>>>(p_sh, p_wh + WOFF_OUT,
        b_out, nullptr, p_tmp, nullptr, nullptr, M, DM, DM, 0);
    // 6. x = LN(v + src2) (+ fp16)
    resid_ln_kernel<<<ROWS, 256>>>(p_v, p_tmp, g1, beta1, p_x, p_xh);
    // 7. h1 = relu(x @ W1^T + bf1) -> fp16 (N=1024)
    mma_gemm_kernel<<<dim3(16, MT), 256, GSM_TOTAL>>>(p_xh, p_wh + WOFF_1,
        bf1, nullptr, nullptr, nullptr, p_h1h, M, DF, DM, 1);
    // 8. h = h1 @ W2^T + bf2 -> g_tmp (K=1024)
    mma_gemm_kernel<<<dim3(4, MT), 256, GSM_TOTAL>>>(p_h1h, p_wh + WOFF_2,
        bf2, nullptr, p_tmp, nullptr, nullptr, M, DM, DF, 0);
    // 9. x = LN(x + h) -> directly into d_out (mapped)
    resid_ln_out_kernel<<<ROWS, 256>>>(p_x, p_tmp, g2, beta2, out);
    // 10. all_vt passthrough
    {
        size_t total = (size_t)NB * 75 * N_VT * DM;
        copy_vt_kernel<<<(unsigned)((total + 255) / 256), 256>>>(all_vt, out);
    }
}